// round 1
// baseline (speedup 1.0000x reference)
#include <cuda_runtime.h>
#include <math.h>

// Problem constants (fixed by the dataset)
#define BB    8
#define CC    128
#define NN    65536
#define NOBJ  64
#define CHUNK 512
#define NCHUNK (NN / CHUNK)   // 128 chunks per batch -> 1024 stage-1 blocks

// Scratch: per-block partial maxes. 8 * 128 * 64 * 128 floats = 32 MB (static device array: allowed)
__device__ float g_partial[(size_t)BB * NCHUNK * NOBJ * CC];
// Detected element stride of box_idx when viewed as int32 (1 = int32, 2 = int64)
__device__ int g_idx_stride;

// ---------------------------------------------------------------------------
// Probe: decide whether box_idx is int32 or int64 (little-endian).
// If int64 with values in [0,64): int32 view = [val,0,val,0,...].
// Reads only 512 int32 words -> safe under either interpretation.
// Deterministic: same input -> same flag every replay.
// ---------------------------------------------------------------------------
__global__ void probe_idx_dtype(const int* __restrict__ idx32) {
    __shared__ int ok;
    if (threadIdx.x == 0) ok = 1;
    __syncthreads();
    int t = threadIdx.x;               // 256 threads
    int lo = idx32[2 * t];
    int hi = idx32[2 * t + 1];
    if (hi != 0 || lo < 0 || lo >= NOBJ) atomicAnd(&ok, 0);
    __syncthreads();
    if (threadIdx.x == 0) g_idx_stride = ok ? 2 : 1;
}

// ---------------------------------------------------------------------------
// Stage 1: per-(batch, point-chunk) segment max.
// 128 threads = 128 channels. Thread t exclusively owns smem column t of
// acc[NOBJ][CC] -> zero atomics, zero bank conflicts (bank = t % 32).
// box_idx is uniform across the block per point -> smem broadcast reads.
// Features: thread t streams its own contiguous row feat[b][t][n0..] as float4.
// ---------------------------------------------------------------------------
__global__ __launch_bounds__(CC) void seg_max_stage1(
    const float* __restrict__ feat, const int* __restrict__ idx32)
{
    __shared__ float acc[NOBJ * CC];          // 32 KB
    __shared__ unsigned char segs[CHUNK];     // 512 B

    const int t     = threadIdx.x;            // channel
    const int chunk = blockIdx.x;
    const int b     = blockIdx.y;
    const int istr  = g_idx_stride;

    #pragma unroll
    for (int s = 0; s < NOBJ; ++s)
        acc[s * CC + t] = -INFINITY;

    const int pbase = b * NN + chunk * CHUNK;
    for (int i = t; i < CHUNK; i += CC)
        segs[i] = (unsigned char)idx32[(pbase + i) * istr];
    __syncthreads();

    const float4* __restrict__ fp =
        (const float4*)(feat + (size_t)(b * CC + t) * NN + (size_t)chunk * CHUNK);

    #pragma unroll 4
    for (int j = 0; j < CHUNK / 4; ++j) {
        float4 v = fp[j];
        int s0 = segs[4 * j + 0];
        int s1 = segs[4 * j + 1];
        int s2 = segs[4 * j + 2];
        int s3 = segs[4 * j + 3];
        acc[s0 * CC + t] = fmaxf(acc[s0 * CC + t], v.x);
        acc[s1 * CC + t] = fmaxf(acc[s1 * CC + t], v.y);
        acc[s2 * CC + t] = fmaxf(acc[s2 * CC + t], v.z);
        acc[s3 * CC + t] = fmaxf(acc[s3 * CC + t], v.w);
    }
    // No barrier needed: each thread reads back only its own column.
    float* __restrict__ outp =
        g_partial + (size_t)(b * NCHUNK + chunk) * (NOBJ * CC);
    #pragma unroll
    for (int s = 0; s < NOBJ; ++s)
        outp[s * CC + t] = acc[s * CC + t];
}

// ---------------------------------------------------------------------------
// Stage 2: reduce the 128 per-chunk partials for each (b, seg, c).
// One thread per output element; coalesced loads (consecutive c contiguous).
// Empty segment (-inf) -> 0, matching the reference's isfinite guard.
// ---------------------------------------------------------------------------
__global__ void seg_max_stage2(float* __restrict__ out) {
    int o = blockIdx.x * blockDim.x + threadIdx.x;   // 0 .. 65535
    int c = o & (CC - 1);
    int g = o >> 7;          // b*NOBJ + s
    int b = g >> 6;
    int s = g & (NOBJ - 1);

    const float* __restrict__ p =
        g_partial + (size_t)b * NCHUNK * (NOBJ * CC) + s * CC + c;

    float m = -INFINITY;
    #pragma unroll 8
    for (int k = 0; k < NCHUNK; ++k)
        m = fmaxf(m, p[(size_t)k * (NOBJ * CC)]);

    out[o] = isfinite(m) ? m : 0.0f;
}

// ---------------------------------------------------------------------------
extern "C" void kernel_launch(void* const* d_in, const int* in_sizes, int n_in,
                              void* d_out, int out_size)
{
    // Identify inputs by element count (robust to ordering):
    //   point_features: 8*128*65536 = 67108864
    //   box_idx       : 8*65536    = 524288
    const float* feat = nullptr;
    const int*   idx  = nullptr;
    for (int i = 0; i < n_in; ++i) {
        if (in_sizes[i] == BB * CC * NN)      feat = (const float*)d_in[i];
        else if (in_sizes[i] == BB * NN)      idx  = (const int*)d_in[i];
    }

    probe_idx_dtype<<<1, 256>>>(idx);

    dim3 g1(NCHUNK, BB);
    seg_max_stage1<<<g1, CC>>>(feat, idx);

    seg_max_stage2<<<out_size / 256, 256>>>((float*)d_out);
}

// round 2
// speedup vs baseline: 2.2687x; 2.2687x over previous
#include <cuda_runtime.h>
#include <math.h>

// Problem constants (fixed by the dataset)
#define BB    8
#define CC    128
#define NN    65536
#define NOBJ  64

#define PBLK     1024              // points per stage-1 block
#define TILE_PT  64                // points per smem tile
#define NTILES   (PBLK / TILE_PT)  // 16
#define NCHUNK   (NN / PBLK)       // 64 stage-1 blocks per batch
#define THREADS1 256               // 128 channels x 2 point-slices
#define NSLICE   2
#define SLICE_PT (TILE_PT / NSLICE)  // 32

// Scratch (static device arrays: allowed)
__device__ float         g_partial[(size_t)BB * NCHUNK * NOBJ * CC];  // 16 MB
__device__ unsigned char g_segs[BB * NN];                             // 512 KB

// ---------------------------------------------------------------------------
// Prep: detect box_idx dtype (int32 vs int64) and convert to uint8 segs.
// Every block independently probes the first 256 (possible) int64 entries:
// if idx is int64 with values in [0,64), the int32 view is [v,0,v,0,...].
// Random int32 data cannot keep all odd words zero -> unambiguous.
// Deterministic: same input -> same result on every replay.
// ---------------------------------------------------------------------------
__global__ void prep_segs(const int* __restrict__ idx32) {
    __shared__ int ok;
    if (threadIdx.x == 0) ok = 1;
    __syncthreads();
    {
        int t  = threadIdx.x;              // 256 threads, reads 512 ints (safe either way)
        int lo = idx32[2 * t];
        int hi = idx32[2 * t + 1];
        if (hi != 0 || lo < 0 || lo >= NOBJ) atomicAnd(&ok, 0);
    }
    __syncthreads();
    const int stride = ok ? 2 : 1;

    const int base = blockIdx.x * 2048;    // 256 blocks x 2048 points = 524288
    #pragma unroll
    for (int k = 0; k < 8; ++k) {
        int i = base + k * 256 + threadIdx.x;
        g_segs[i] = (unsigned char)idx32[(size_t)i * stride];
    }
}

// ---------------------------------------------------------------------------
// Stage 1: per-(batch, 1024-point chunk) segment max.
//
// Per tile of 64 points:
//  LOAD  : all 256 threads cooperatively load feat rows COALESCED (float4,
//          4 lines per LDG.128) and scatter into tile[pt][c ^ (pt&31)].
//          XOR swizzle -> conflict-free store AND conflict-free transposed read.
//  COMPUTE: thread = (channel c, slice q). Slice q handles 32 points; reads
//          tile transposed (conflict-free), RMWs its private acc copy at
//          acc[q][s][c] -- s uniform across the warp, lanes = consecutive c
//          -> zero bank conflicts, zero atomics, no cross-warp races.
// ---------------------------------------------------------------------------
extern __shared__ float smem1[];

__global__ __launch_bounds__(THREADS1) void seg_max_stage1(
    const float* __restrict__ feat)
{
    float* acc  = smem1;                          // [NSLICE][NOBJ][CC]  64 KB
    float* tile = smem1 + NSLICE * NOBJ * CC;     // [TILE_PT][CC]       32 KB
    int*   segs = (int*)(tile + TILE_PT * CC);    // [TILE_PT]          256 B

    const int tid = threadIdx.x;
    const int c   = tid & (CC - 1);
    const int q   = tid >> 7;                     // slice (warp-uniform)
    const int b   = blockIdx.y;
    const int n0  = blockIdx.x * PBLK;

    for (int i = tid; i < NSLICE * NOBJ * CC; i += THREADS1)
        acc[i] = -INFINITY;
    __syncthreads();

    float* const accq = acc + q * (NOBJ * CC) + c;

    for (int tIdx = 0; tIdx < NTILES; ++tIdx) {
        const int p0 = n0 + tIdx * TILE_PT;

        if (tid < TILE_PT) segs[tid] = g_segs[b * NN + p0 + tid];

        // Coalesced tile load: 8192 floats = 2048 float4, 8 per thread.
        // idx -> (channel row cr = idx>>4, point-quad pt4 = idx&15):
        // lanes sweep pt4 fastest -> contiguous 128B segments per row.
        #pragma unroll
        for (int k = 0; k < 8; ++k) {
            int idx = tid + k * THREADS1;
            int cr  = idx >> 4;
            int pt4 = idx & 15;
            float4 v = *(const float4*)(feat + ((size_t)(b * CC + cr)) * NN
                                             + p0 + pt4 * 4);
            int p = pt4 * 4;
            tile[(p + 0) * CC + (cr ^ ((p + 0) & 31))] = v.x;
            tile[(p + 1) * CC + (cr ^ ((p + 1) & 31))] = v.y;
            tile[(p + 2) * CC + (cr ^ ((p + 2) & 31))] = v.z;
            tile[(p + 3) * CC + (cr ^ ((p + 3) & 31))] = v.w;
        }
        __syncthreads();

        // Transposed compute: conflict-free LDS + conflict-free smem RMW.
        #pragma unroll
        for (int j = 0; j < SLICE_PT; ++j) {
            int   pt = q * SLICE_PT + j;
            int   s  = segs[pt];                          // uniform per warp
            float v  = tile[pt * CC + (c ^ (pt & 31))];
            float* a = accq + s * CC;
            *a = fmaxf(*a, v);
        }
        __syncthreads();
    }

    // Merge the two slice copies, write partials (coalesced).
    float* outp = g_partial + (size_t)(b * NCHUNK + blockIdx.x) * (NOBJ * CC);
    for (int i = tid; i < NOBJ * CC; i += THREADS1)
        outp[i] = fmaxf(acc[i], acc[NOBJ * CC + i]);
}

// ---------------------------------------------------------------------------
// Stage 2: reduce the 64 per-chunk partials per (b, seg, c); -inf -> 0 guard.
// Consecutive threads = consecutive c -> fully coalesced loads.
// ---------------------------------------------------------------------------
__global__ void seg_max_stage2(float* __restrict__ out) {
    int o = blockIdx.x * blockDim.x + threadIdx.x;   // 0 .. 65535
    int c = o & (CC - 1);
    int g = o >> 7;
    int b = g >> 6;
    int s = g & (NOBJ - 1);

    const float* __restrict__ p =
        g_partial + (size_t)b * NCHUNK * (NOBJ * CC) + s * CC + c;

    float m = -INFINITY;
    #pragma unroll 8
    for (int k = 0; k < NCHUNK; ++k)
        m = fmaxf(m, p[(size_t)k * (NOBJ * CC)]);

    out[o] = isfinite(m) ? m : 0.0f;
}

// ---------------------------------------------------------------------------
extern "C" void kernel_launch(void* const* d_in, const int* in_sizes, int n_in,
                              void* d_out, int out_size)
{
    const float* feat = nullptr;
    const int*   idx  = nullptr;
    for (int i = 0; i < n_in; ++i) {
        if (in_sizes[i] == BB * CC * NN)  feat = (const float*)d_in[i];
        else if (in_sizes[i] == BB * NN)  idx  = (const int*)d_in[i];
    }

    static int smem_set = 0;
    const int smem_bytes = (NSLICE * NOBJ * CC + TILE_PT * CC) * 4 + TILE_PT * 4;
    if (!smem_set) {
        cudaFuncSetAttribute(seg_max_stage1,
                             cudaFuncAttributeMaxDynamicSharedMemorySize,
                             smem_bytes);
        smem_set = 1;
    }

    prep_segs<<<256, 256>>>(idx);

    dim3 g1(NCHUNK, BB);
    seg_max_stage1<<<g1, THREADS1, smem_bytes>>>(feat);

    seg_max_stage2<<<out_size / 256, 256>>>((float*)d_out);
}

// round 4
// speedup vs baseline: 2.7799x; 1.2254x over previous
#include <cuda_runtime.h>
#include <math.h>
#include <stdint.h>

// Problem constants
#define BB    8
#define CC    128
#define NN    65536
#define NOBJ  64

#define PBLK     512                 // points per stage-1 block
#define TILE_PT  32                  // points per smem tile (128B rows)
#define NTILES   (PBLK / TILE_PT)    // 16
#define NCHUNK   (NN / PBLK)         // 128 -> 1024 stage-1 blocks
#define THREADS1 256
#define NSLICE   2                   // two 128-thread point-slices
#define SLICE_PT (TILE_PT / NSLICE)  // 16 points per thread per tile

// Scratch (static device arrays: allowed)
__device__ float         g_partial[(size_t)BB * NCHUNK * NOBJ * CC]; // 32 MB (L2-resident)
__device__ unsigned char g_segs[BB * NN];                            // 512 KB

// ---- cp.async helpers ------------------------------------------------------
__device__ __forceinline__ void cp_async16(uint32_t dst, const void* src) {
    asm volatile("cp.async.cg.shared.global [%0], [%1], 16;\n" :: "r"(dst), "l"(src));
}
__device__ __forceinline__ void cp_commit() { asm volatile("cp.async.commit_group;\n"); }
template <int N> __device__ __forceinline__ void cp_wait() {
    asm volatile("cp.async.wait_group %0;\n" :: "n"(N));
}

// ---------------------------------------------------------------------------
// Prep: detect box_idx dtype (int32 vs int64 little-endian) and convert to u8.
// int64 values in [0,64) -> int32 view [v,0,v,0,...]; random int32 cannot keep
// all 256 odd words zero. Deterministic across replays.
// ---------------------------------------------------------------------------
__global__ void prep_segs(const int* __restrict__ idx32) {
    __shared__ int ok;
    if (threadIdx.x == 0) ok = 1;
    __syncthreads();
    {
        int t  = threadIdx.x;                     // reads 512 ints (safe either way)
        int lo = idx32[2 * t];
        int hi = idx32[2 * t + 1];
        if (hi != 0 || lo < 0 || lo >= NOBJ) atomicAnd(&ok, 0);
    }
    __syncthreads();

    int p = (blockIdx.x * 256 + threadIdx.x) * 4;  // 512 blocks -> 524288 points
    uchar4 r;
    if (ok) {  // int64: 4 points = 2x int4
        int4 a = ((const int4*)idx32)[p / 2];
        int4 b = ((const int4*)idx32)[p / 2 + 1];
        r = make_uchar4((unsigned char)a.x, (unsigned char)a.z,
                        (unsigned char)b.x, (unsigned char)b.z);
    } else {   // int32: 4 points = 1x int4
        int4 a = ((const int4*)idx32)[p / 4];
        r = make_uchar4((unsigned char)a.x, (unsigned char)a.y,
                        (unsigned char)a.z, (unsigned char)a.w);
    }
    *(uchar4*)(g_segs + p) = r;
}

// ---------------------------------------------------------------------------
// Stage 1: per-(batch, 512-point chunk) segment max.
//   Tile layout: tile[buf][c][pt], 128B rows, 16B swizzle pt4 ^= (c&7).
//   Load  : cp.async double-buffered, coalesced (4 lines / 512B warp op).
//   Compute: thread (c, q); LDS.128 -> 4 conflict-free acc RMWs.
//            acc[q][s][c]: s warp-uniform, lanes = consecutive c -> 0 conflicts,
//            0 atomics, slices own disjoint points -> 0 races.
//   Drain fix: final iteration must wait_group 0 (wait_group 1 is a no-op when
//   only one group remains pending -> stale last tile, the Round-3 bug).
// ---------------------------------------------------------------------------
extern __shared__ float smem1[];

__global__ __launch_bounds__(THREADS1) void seg_max_stage1(
    const float* __restrict__ feat)
{
    float* acc  = smem1;                              // [2][NOBJ][CC]   64 KB
    float* tile = smem1 + NSLICE * NOBJ * CC;         // [2][CC][TILE_PT] 32 KB
    unsigned int* segw = (unsigned int*)(tile + 2 * CC * TILE_PT); // [PBLK/4]

    const int tid = threadIdx.x;
    const int c   = tid & (CC - 1);
    const int q   = tid >> 7;                         // warp-uniform
    const int b   = blockIdx.y;
    const int n0  = blockIdx.x * PBLK;
    const float* fbase = feat + (size_t)b * CC * NN + n0;

    // init acc (float4)
    #pragma unroll
    for (int i = tid; i < NSLICE * NOBJ * CC / 4; i += THREADS1)
        ((float4*)acc)[i] = make_float4(-INFINITY, -INFINITY, -INFINITY, -INFINITY);
    // block's segs: 512 B
    if (tid < PBLK / 4)
        segw[tid] = ((const unsigned int*)(g_segs + b * NN + n0))[tid];

    const uint32_t tile_u = (uint32_t)__cvta_generic_to_shared(tile);

    auto prefetch = [&](int t) {
        const uint32_t base = tile_u + (t & 1) * (CC * TILE_PT * 4);
        #pragma unroll
        for (int k = 0; k < 4; ++k) {
            int idx = k * THREADS1 + tid;             // 0..1023 float4 slots
            int cr  = idx >> 3;                       // channel row
            int pt4 = idx & 7;                        // 16B group in row
            uint32_t dst = base + cr * (TILE_PT * 4) + (((pt4 ^ (cr & 7))) << 4);
            cp_async16(dst, fbase + (size_t)cr * NN + t * TILE_PT + pt4 * 4);
        }
        cp_commit();
    };

    prefetch(0);
    prefetch(1);
    __syncthreads();   // acc init + segw visible to all

    float* const a0 = acc + q * (NOBJ * CC) + c;

    for (int t = 0; t < NTILES; ++t) {
        // Drain rule: ensure group t is complete. For t == NTILES-1 the
        // pending set is only {g15}, so wait_group 1 would be a no-op.
        if (t < NTILES - 1) cp_wait<1>();
        else                cp_wait<0>();
        __syncthreads();

        const float* tb = tile + (t & 1) * (CC * TILE_PT);
        #pragma unroll
        for (int g4 = 0; g4 < SLICE_PT / 4; ++g4) {   // 4 point-quads
            const int pt4 = q * (SLICE_PT / 4) + g4;
            const unsigned int sw = segw[t * (TILE_PT / 4) + pt4]; // uniform bcast
            float4 v = *(const float4*)(tb + c * TILE_PT + ((pt4 ^ (c & 7)) << 2));
            float* a;
            a = a0 + ( sw        & 0xFF) * CC;  *a = fmaxf(*a, v.x);
            a = a0 + ((sw >> 8)  & 0xFF) * CC;  *a = fmaxf(*a, v.y);
            a = a0 + ((sw >> 16) & 0xFF) * CC;  *a = fmaxf(*a, v.z);
            a = a0 + ( sw >> 24        ) * CC;  *a = fmaxf(*a, v.w);
        }
        __syncthreads();                  // all reads of this buffer done
        if (t + 2 < NTILES) prefetch(t + 2);
    }

    // merge the two slice copies, write partials (coalesced float4)
    float* outp = g_partial + (size_t)(b * NCHUNK + blockIdx.x) * (NOBJ * CC);
    #pragma unroll
    for (int i = tid; i < NOBJ * CC / 4; i += THREADS1) {
        float4 x = ((const float4*)acc)[i];
        float4 y = ((const float4*)acc)[NOBJ * CC / 4 + i];
        x.x = fmaxf(x.x, y.x); x.y = fmaxf(x.y, y.y);
        x.z = fmaxf(x.z, y.z); x.w = fmaxf(x.w, y.w);
        ((float4*)outp)[i] = x;
    }
}

// ---------------------------------------------------------------------------
// Stage 2: reduce 128 per-chunk partials per (b, seg, c-quad); -inf -> 0.
// ---------------------------------------------------------------------------
__global__ void seg_max_stage2(float* __restrict__ out) {
    int o4 = blockIdx.x * blockDim.x + threadIdx.x;   // 0..16383 float4s
    int c4 = o4 & (CC / 4 - 1);
    int g  = o4 >> 5;
    int b  = g >> 6;
    int s  = g & (NOBJ - 1);

    const float4* __restrict__ p =
        (const float4*)(g_partial + (size_t)b * NCHUNK * (NOBJ * CC) + s * CC) + c4;

    float4 m = make_float4(-INFINITY, -INFINITY, -INFINITY, -INFINITY);
    #pragma unroll 4
    for (int k = 0; k < NCHUNK; ++k) {
        float4 v = p[(size_t)k * (NOBJ * CC / 4)];
        m.x = fmaxf(m.x, v.x); m.y = fmaxf(m.y, v.y);
        m.z = fmaxf(m.z, v.z); m.w = fmaxf(m.w, v.w);
    }
    float4 r;
    r.x = isfinite(m.x) ? m.x : 0.0f;
    r.y = isfinite(m.y) ? m.y : 0.0f;
    r.z = isfinite(m.z) ? m.z : 0.0f;
    r.w = isfinite(m.w) ? m.w : 0.0f;
    ((float4*)out)[o4] = r;
}

// ---------------------------------------------------------------------------
extern "C" void kernel_launch(void* const* d_in, const int* in_sizes, int n_in,
                              void* d_out, int out_size)
{
    const float* feat = nullptr;
    const int*   idx  = nullptr;
    for (int i = 0; i < n_in; ++i) {
        if (in_sizes[i] == BB * CC * NN)  feat = (const float*)d_in[i];
        else if (in_sizes[i] == BB * NN)  idx  = (const int*)d_in[i];
    }

    const int smem_bytes = (NSLICE * NOBJ * CC + 2 * CC * TILE_PT) * 4 + (PBLK / 4) * 4;
    static int smem_set = 0;
    if (!smem_set) {
        cudaFuncSetAttribute(seg_max_stage1,
                             cudaFuncAttributeMaxDynamicSharedMemorySize,
                             smem_bytes);
        smem_set = 1;
    }

    prep_segs<<<512, 256>>>(idx);

    dim3 g1(NCHUNK, BB);
    seg_max_stage1<<<g1, THREADS1, smem_bytes>>>(feat);

    seg_max_stage2<<<(BB * NOBJ * CC / 4) / 256, 256>>>((float*)d_out);
}